// round 12
// baseline (speedup 1.0000x reference)
#include <cuda_runtime.h>
#include <cuda_bf16.h>
#include <cstdint>

#define BB 16
#define NN 256
#define DD 512
#define PE_ROWS 64           // pos = t - start < x[b,seg] <= 63 -> pos in [0,62]
#define PE_BYTES (PE_ROWS * DD * 4)   // 131072

// 256-bit global stores (sm_100+): one instruction commits 1 KB/warp.
__device__ __forceinline__ void stg256(float* p, float4 a, float4 b) {
    asm volatile("st.global.v8.f32 [%0], {%1,%2,%3,%4,%5,%6,%7,%8};"
                 :: "l"(p), "f"(a.x), "f"(a.y), "f"(a.z), "f"(a.w),
                    "f"(b.x), "f"(b.y), "f"(b.z), "f"(b.w)
                 : "memory");
}

__device__ __forceinline__ uint32_t smem_u32(const void* p) {
    uint32_t a;
    asm("{ .reg .u64 t; cvta.to.shared.u64 t, %1; cvt.u32.u64 %0, t; }"
        : "=r"(a) : "l"(p));
    return a;
}

// Persistent kernel, write-wall bound (~4.7 TB/s DRAM steady state).
// Prologue: ONE cp.async.bulk (TMA) pulls the 128 KB hot pos_enc table into
// smem while the 16 warps concurrently compute the cumsum — copy and scan
// overlap, then a single mbarrier wait. Hot loop: warps own contiguous row
// ranges; one binary search, monotone segment advance, 4x LDS.128 ->
// 2x STG.256 per row (plain write-back). Tail rows store register zeros.
__global__ __launch_bounds__(1024, 1)
void pe_gather_kernel(const int* __restrict__ x,
                      const float* __restrict__ pos_enc,
                      float* __restrict__ out, int T, int chunk) {
    extern __shared__ float smem[];
    float*    s_pe  = smem;                              // PE_ROWS*DD floats (128 KB)
    int*      s_cum = (int*)(smem + PE_ROWS * DD);       // BB*NN ints (16 KB)
    uint64_t* s_mbar = (uint64_t*)(s_cum + BB * NN);     // mbarrier (8 B)

    const int warp = threadIdx.x >> 5;
    const int lane = threadIdx.x & 31;
    const uint32_t mbar_u = smem_u32(s_mbar);

    // ---- init mbarrier, then launch async 128 KB hot-table copy ----
    if (threadIdx.x == 0) {
        asm volatile("mbarrier.init.shared.b64 [%0], 1;" :: "r"(mbar_u) : "memory");
    }
    __syncthreads();
    if (threadIdx.x == 0) {
        asm volatile("mbarrier.arrive.expect_tx.shared.b64 _, [%0], %1;"
                     :: "r"(mbar_u), "r"((uint32_t)PE_BYTES) : "memory");
        asm volatile("cp.async.bulk.shared::cta.global.mbarrier::complete_tx::bytes "
                     "[%0], [%1], %2, [%3];"
                     :: "r"(smem_u32(s_pe)), "l"(pos_enc),
                        "r"((uint32_t)PE_BYTES), "r"(mbar_u) : "memory");
    }

    // ---- cumsum of x overlaps the bulk copy: warps 0..15, one batch row each ----
    if (warp < BB) {
        int carry = 0;
        for (int c = 0; c < NN / 32; c++) {
            int idx = c * 32 + lane;
            int v = x[warp * NN + idx];
            #pragma unroll
            for (int off = 1; off < 32; off <<= 1) {
                int n = __shfl_up_sync(0xffffffffu, v, off);
                if (lane >= off) v += n;
            }
            v += carry;
            s_cum[warp * NN + idx] = v;
            carry = __shfl_sync(0xffffffffu, v, 31);
        }
    }
    __syncthreads();                                     // cumsum visible to all

    // ---- wait for the hot table ----
    {
        uint32_t done;
        asm volatile(
            "{\n\t.reg .pred p;\n\t"
            "mbarrier.try_wait.parity.acquire.cta.shared::cta.b64 p, [%1], 0;\n\t"
            "selp.b32 %0, 1, 0, p;\n\t}"
            : "=r"(done) : "r"(mbar_u) : "memory");
        if (!done) {
            asm volatile(
                "{\n\t.reg .pred P1;\n\t"
                "WL_%=:\n\t"
                "mbarrier.try_wait.parity.acquire.cta.shared::cta.b64 P1, [%0], 0, 0x989680;\n\t"
                "@P1 bra.uni WD_%=;\n\t"
                "bra.uni WL_%=;\n\t"
                "WD_%=:\n\t}"
                :: "r"(mbar_u) : "memory");
        }
    }

    // ---- contiguous row range for this warp ----
    const long total = (long)BB * T;
    const int warp_global = blockIdx.x * (blockDim.x >> 5) + warp;
    long r0 = (long)warp_global * chunk;
    if (r0 >= total) return;
    long r1 = r0 + chunk; if (r1 > total) r1 = total;

    int b = (int)(r0 / T);            // only division in the kernel
    int t = (int)(r0 - (long)b * T);
    const int* cum = s_cum + b * NN;
    int last = cum[NN - 1];

    // searchsorted(cum, t, 'right'): first seg with cum[seg] > t (257 answers -> 9 steps)
    int seg;
    {
        int lo = 0, hi = NN;
        #pragma unroll
        for (int it = 0; it < 9; it++) {
            if (lo < hi) {
                int mid = (lo + hi) >> 1;
                if (cum[mid] <= t) lo = mid + 1; else hi = mid;
            }
        }
        seg = lo;
    }

    const float4 z = make_float4(0.f, 0.f, 0.f, 0.f);

    for (long r = r0; r < r1; r++) {
        // lane l owns floats [8l, 8l+8) and [256+8l, 256+8l+8) of the row
        float* dst = out + r * (long)DD + lane * 8;

        if (t >= last) {
            stg256(dst,       z, z);
            stg256(dst + 256, z, z);
        } else {
            while (cum[seg] <= t) seg++;                 // monotone advance
            const int start = (seg > 0) ? cum[seg - 1] : 0;
            const int pos = t - start;                   // [0, 62]
            const float4* src = (const float4*)(s_pe + pos * DD) + lane * 2;
            float4 v0 = src[0];
            float4 v1 = src[1];
            float4 v2 = src[64];     // +256 floats
            float4 v3 = src[65];
            stg256(dst,       v0, v1);
            stg256(dst + 256, v2, v3);
        }

        if (++t == T) {                                  // batch-row boundary
            t = 0; b++;
            if (b < BB) { cum += NN; last = cum[NN - 1]; seg = 0; }
            else break;
        }
    }
}

extern "C" void kernel_launch(void* const* d_in, const int* in_sizes, int n_in,
                              void* d_out, int out_size) {
    const int*   x       = (const int*)d_in[0];
    const float* pos_enc = (const float*)d_in[1];
    float*       out     = (float*)d_out;

    const int T = out_size / (BB * DD);

    int sms = 148;
    cudaDeviceGetAttribute(&sms, cudaDevAttrMultiProcessorCount, 0);

    const long total = (long)BB * T;
    const int nwarps = sms * 32;
    const int chunk = (int)((total + nwarps - 1) / nwarps);

    const size_t smem_bytes = (size_t)(PE_ROWS * DD) * sizeof(float)
                            + (size_t)(BB * NN) * sizeof(int)
                            + 16;                         // mbarrier slot
    cudaFuncSetAttribute(pe_gather_kernel,
                         cudaFuncAttributeMaxDynamicSharedMemorySize,
                         (int)smem_bytes);
    pe_gather_kernel<<<sms, 1024, smem_bytes>>>(x, pos_enc, out, T, chunk);
}